// round 14
// baseline (speedup 1.0000x reference)
#include <cuda_runtime.h>
#include <cstdint>

// Problem constants
#define Bsz 32
#define Lsz 4096
#define Isz 128
#define Hsz 256
#define Osz 128
#define NDELAY 5      // delay line length (DELAY+1)
#define LH (Lsz * Hsz)   // per-batch-row stride in elements

// Scratch (static device globals: allocation-free per harness rules)
__device__ float g_xz[Bsz * Lsz * Hsz];
__device__ float g_xh[Bsz * Lsz * Hsz];
__device__ float g_hs[Bsz * Lsz * Hsz];

// ---------------------------------------------------------------------------
// fp32 tiled GEMM with bias, packed f32x2 accumulation.
// C[M,N] = A[M,K] @ B[K,N] + bias[N]; 64x64 tile, 256 threads, 4x4 micro.
// ---------------------------------------------------------------------------
__global__ void __launch_bounds__(256) gemm_bias(
    const float* __restrict__ A, const float* __restrict__ Bm,
    const float* __restrict__ bias, float* __restrict__ C,
    int M, int K, int N)
{
    __shared__ float sA[64][68];
    __shared__ float sB[64][68];

    const int m0  = blockIdx.x << 6;
    const int n0  = blockIdx.y << 6;
    const int tid = threadIdx.x;
    const int tx  = tid & 15;
    const int ty  = tid >> 4;

    uint64_t acc01[4], acc23[4];
#pragma unroll
    for (int i = 0; i < 4; i++) { acc01[i] = 0; acc23[i] = 0; }

    for (int kk = 0; kk < K; kk += 64) {
#pragma unroll
        for (int i = 0; i < 4; i++) {
            int lin = tid + (i << 8);
            int r   = lin >> 4;
            int c   = (lin & 15) << 2;
            *(float4*)&sA[r][c] = *(const float4*)&A[(size_t)(m0 + r) * K + kk + c];
            *(float4*)&sB[r][c] = *(const float4*)&Bm[(size_t)(kk + r) * N + n0 + c];
        }
        __syncthreads();

#pragma unroll 16
        for (int k = 0; k < 64; k++) {
            ulonglong2 bb = *(const ulonglong2*)&sB[k][tx << 2];
#pragma unroll
            for (int i = 0; i < 4; i++) {
                float a = sA[(ty << 2) + i][k];
                uint64_t aa;
                asm("mov.b64 %0, {%1, %1};" : "=l"(aa) : "f"(a));
                asm("fma.rn.f32x2 %0, %1, %2, %0;" : "+l"(acc01[i]) : "l"(aa), "l"(bb.x));
                asm("fma.rn.f32x2 %0, %1, %2, %0;" : "+l"(acc23[i]) : "l"(aa), "l"(bb.y));
            }
        }
        __syncthreads();
    }

    float4 bb = *(const float4*)&bias[n0 + (tx << 2)];
#pragma unroll
    for (int i = 0; i < 4; i++) {
        float c0, c1, c2, c3;
        asm("mov.b64 {%0, %1}, %2;" : "=f"(c0), "=f"(c1) : "l"(acc01[i]));
        asm("mov.b64 {%0, %1}, %2;" : "=f"(c2), "=f"(c3) : "l"(acc23[i]));
        float4 o;
        o.x = c0 + bb.x; o.y = c1 + bb.y; o.z = c2 + bb.z; o.w = c3 + bb.w;
        *(float4*)&C[(size_t)(m0 + (ty << 2) + i) * N + n0 + (tx << 2)] = o;
    }
}

// ---------------------------------------------------------------------------
// Fast-math helpers (ex2/rcp approx: rel err ~1e-7)
// ---------------------------------------------------------------------------
__device__ __forceinline__ float ex2_fast(float x) {
    float r; asm("ex2.approx.f32 %0, %1;" : "=f"(r) : "f"(x)); return r;
}
__device__ __forceinline__ float rcp_fast(float x) {
    float r; asm("rcp.approx.f32 %0, %1;" : "=f"(r) : "f"(x)); return r;
}
__device__ __forceinline__ float sigmoid_fast(float x) {
    return rcp_fast(1.f + ex2_fast(-1.4426950408889634f * x));
}
__device__ __forceinline__ float tanh_fast(float x) {
    float e = ex2_fast(2.885390081777927f * x);
    return (e - 1.f) * rcp_fast(e + 1.f);
}

// Packed f32x2 dot over 64 floats; all lanes read the SAME addresses
// (whole-warp broadcast -> conflict-free, 1 wavefront per LDS.128).
__device__ __forceinline__ float dot64_bcast(const float* p, const uint64_t* w) {
    const ulonglong2* v = (const ulonglong2*)p;
    uint64_t a0 = 0, a1 = 0, a2 = 0, a3 = 0;
#pragma unroll
    for (int j = 0; j < 8; j++) {
        ulonglong2 t = v[j];
        asm("fma.rn.f32x2 %0, %1, %2, %0;" : "+l"(a0) : "l"(t.x), "l"(w[2*j]));
        asm("fma.rn.f32x2 %0, %1, %2, %0;" : "+l"(a1) : "l"(t.y), "l"(w[2*j+1]));
    }
#pragma unroll
    for (int j = 8; j < 16; j++) {
        ulonglong2 t = v[j];
        asm("fma.rn.f32x2 %0, %1, %2, %0;" : "+l"(a2) : "l"(t.x), "l"(w[2*j]));
        asm("fma.rn.f32x2 %0, %1, %2, %0;" : "+l"(a3) : "l"(t.y), "l"(w[2*j+1]));
    }
    uint64_t s01, s23, s;
    asm("add.rn.f32x2 %0, %1, %2;" : "=l"(s01) : "l"(a0), "l"(a1));
    asm("add.rn.f32x2 %0, %1, %2;" : "=l"(s23) : "l"(a2), "l"(a3));
    asm("add.rn.f32x2 %0, %1, %2;" : "=l"(s)   : "l"(s01), "l"(s23));
    float lo, hi;
    asm("mov.b64 {%0, %1}, %2;" : "=f"(lo), "=f"(hi) : "l"(s));
    return lo + hi;
}

__device__ __forceinline__ uint64_t pack2(float lo, float hi) {
    uint64_t r; asm("mov.b64 %0, {%1, %2};" : "=l"(r) : "f"(lo), "f"(hi)); return r;
}

__device__ __forceinline__ void mbar_expect_tx(uint32_t mbar, uint32_t bytes) {
    asm volatile("mbarrier.arrive.expect_tx.shared.b64 _, [%0], %1;"
                 :: "r"(mbar), "r"(bytes) : "memory");
}

__device__ __forceinline__ void mbar_wait(uint32_t mbar, uint32_t parity) {
    asm volatile(
        "{\n\t"
        ".reg .pred P;\n\t"
        "WAIT_%=:\n\t"
        "mbarrier.try_wait.parity.acquire.cluster.shared::cta.b64 P, [%0], %1, 10000000;\n\t"
        "@!P bra WAIT_%=;\n\t"
        "}"
        :: "r"(mbar), "r"(parity) : "memory");
}

// DSMEM bulk copy: local smem -> peer smem, complete_tx to peer's mbarrier.
__device__ __forceinline__ void bulk_s2s(uint32_t dst, uint32_t src,
                                         uint32_t bytes, uint32_t mbar) {
    asm volatile(
        "cp.async.bulk.shared::cluster.shared::cta.mbarrier::complete_tx::bytes "
        "[%0], [%1], %2, [%3];"
        :: "r"(dst), "r"(src), "r"(bytes), "r"(mbar) : "memory");
}

__device__ __forceinline__ void fence_async() {
    asm volatile("fence.proxy.async.shared::cta;" ::: "memory");
}

// ---------------------------------------------------------------------------
// Sequential MGRU scan — R10 dataflow, 2 sequences interleaved per cluster.
//
// 16 clusters x 4 CTAs; cluster c handles batch rows 2c (seq0) and 2c+1
// (seq1) with the SAME register-resident weights. Per step t and seq s the
// exchange is exactly R10's (proven fastest): both partials computed, staged
// ([dst CTA][pUh64|pUz64]), full __syncthreads, tid<4 push 512B per dest
// onto mb[s][t&1] (2048 tx-bytes). Seq1's compute+stage+push sits between
// seq0's push and seq0's consume, hiding seq0's DSMEM flight.
//
// Safety: per-seq private buffers/barriers; each seq's reuse chains are
// verbatim R10's, routed through the shared end-of-step __syncthreads.
// A peer's tx for step t+2 on mb[s][p] requires its end-sync(t+1), which
// requires our push(s,t+1), which follows our end-sync(t), which follows
// our wait(s,t) — so phase t is always consumed before phase t+2 traffic.
// ---------------------------------------------------------------------------
__global__ void __launch_bounds__(256, 1) __cluster_dims__(4, 1, 1)
mgru_scan(const float* __restrict__ xz, const float* __restrict__ xh,
          const float* __restrict__ Uz, const float* __restrict__ Uh,
          float* __restrict__ hs)
{
    __shared__ __align__(16) float a_loc[2][2][64];        // [seq][par][64]
    __shared__ __align__(16) float hd_ring[2][NDELAY][64]; // [seq][slot][64]
    __shared__ __align__(16) float stage[2][2][512];       // [seq][par][...]
    __shared__ __align__(16) float inbox[2][2][512];       // [seq][par][...]
    __shared__ __align__(8) unsigned long long mb[2][2];   // [seq][par]

    const int rank = blockIdx.x & 3;
    const int cl   = blockIdx.x >> 2;       // cluster id 0..15
    const int tid  = threadIdx.x;
    const int lane = tid & 31;
    const int jp   = tid;                   // partial column (global, 0..255)
    const int pr   = tid >> 6;              // destination CTA (owner of jp)
    const int idx  = tid & 63;              // index within destination slice
    const int ks   = tid & 3;               // push peer for tid<4

    // Register-resident weight slices: rows k in G=[64*rank,..+64), column jp.
    uint64_t wz2[32], wh2[32];
    {
        const float* uz = Uz + (size_t)(rank * 64) * Hsz + jp;
        const float* uh = Uh + (size_t)(rank * 64) * Hsz + jp;
#pragma unroll
        for (int i = 0; i < 32; i++) {
            wz2[i] = pack2(uz[(size_t)(2*i) * Hsz], uz[(size_t)(2*i+1) * Hsz]);
            wh2[i] = pack2(uh[(size_t)(2*i) * Hsz], uh[(size_t)(2*i+1) * Hsz]);
        }
    }

    if (tid == 0) {
        uint32_t m0 = (uint32_t)__cvta_generic_to_shared(&mb[0][0]);
#pragma unroll
        for (int i = 0; i < 4; i++)
            asm volatile("mbarrier.init.shared.b64 [%0], 1;"
                         :: "r"(m0 + i * 8) : "memory");
    }
    for (int i = tid; i < 2 * 2 * 64;      i += 256) (&a_loc[0][0][0])[i]   = 0.f;
    for (int i = tid; i < 2 * NDELAY * 64; i += 256) (&hd_ring[0][0][0])[i] = 0.f;
    for (int i = tid; i < 2 * 2 * 512;     i += 256) (&stage[0][0][0])[i]   = 0.f;
    for (int i = tid; i < 2 * 2 * 512;     i += 256) (&inbox[0][0][0])[i]   = 0.f;
    __syncthreads();
    // all CTAs' mbarriers + zeroed buffers visible before any DSMEM traffic
    asm volatile("barrier.cluster.arrive.aligned;" ::: "memory");
    asm volatile("barrier.cluster.wait.aligned;" ::: "memory");

    const uint32_t stage_sa = (uint32_t)__cvta_generic_to_shared(&stage[0][0][0]);
    const uint32_t inbox_sa = (uint32_t)__cvta_generic_to_shared(&inbox[0][0][0]);
    const uint32_t mb_sa    = (uint32_t)__cvta_generic_to_shared(&mb[0][0]);
    uint32_t peer_inbox = 0, peer_mb = 0;   // in CTA `ks`'s SMEM (tid 0..3)
    asm("mapa.shared::cluster.u32 %0, %1, %2;" : "=r"(peer_inbox) : "r"(inbox_sa), "r"(ks));
    asm("mapa.shared::cluster.u32 %0, %1, %2;" : "=r"(peer_mb)    : "r"(mb_sa),    "r"(ks));

    // Column-owner state (threads 0..63): jglob = 64*rank + tid; seq0 = row 2cl
    const int jglob = rank * 64 + tid;
    const float* xzp = xz + (size_t)(2 * cl) * LH + jglob;
    const float* xhp = xh + (size_t)(2 * cl) * LH + jglob;
    float*       hsp = hs + (size_t)(2 * cl) * LH + jglob;

    float h0 = 0.f, z0 = 0.f, xh_cur0 = 0.f, xz_nxt0 = 0.f, xh_nxt0 = 0.f;
    float h1 = 0.f, z1 = 0.f, xh_cur1 = 0.f, xz_nxt1 = 0.f, xh_nxt1 = 0.f;
    if (tid < 64) {
        xh_cur0 = xhp[0];        xh_cur1 = xhp[LH];
        xz_nxt0 = xzp[Hsz];      xz_nxt1 = xzp[LH + Hsz];
        xh_nxt0 = xhp[Hsz];      xh_nxt1 = xhp[LH + Hsz];
        z0 = sigmoid_fast(xzp[0]);        // z(0): h(-5) = 0
        z1 = sigmoid_fast(xzp[LH]);
        // a(0) = z(0)*h(-1) = 0 -> a_loc zeroed
    }

    int slot_r = 1;  // (t+1)%5 : read h(t-4) feeding z(t+1)
    int slot_w = 0;  // t%5     : write h(t)

    for (int t = 0; t < Lsz; ++t) {
        const int p = t & 1;
        const uint32_t q   = (uint32_t)((t >> 1) & 1);
        const uint32_t off0 = (uint32_t)(p << 11);            // seq0, par p
        const uint32_t off1 = (uint32_t)((2 + p) << 11);      // seq1, par p
        const uint32_t mb0  = (uint32_t)(p << 3);
        const uint32_t mb1  = (uint32_t)((2 + p) << 3);

        // ================= seq 0: compute + stage + push =================
        {
            float pUh = dot64_bcast(&a_loc[0][p][0], wh2);
            float pUz = dot64_bcast(&hd_ring[0][slot_r][0], wz2);
            stage[0][p][pr * 128 + idx]      = pUh;
            stage[0][p][pr * 128 + 64 + idx] = pUz;
        }
        __syncthreads();
        if (tid < 4) {
            fence_async();
            bulk_s2s(peer_inbox + off0 + (uint32_t)(rank << 9),
                     stage_sa   + off0 + (uint32_t)(ks << 9),
                     512u, peer_mb + mb0);
        }
        if (tid == 0) mbar_expect_tx(mb_sa + mb0, 2048u);

        // ======== seq 1: compute + stage + push (hides seq0 flight) ======
        {
            float pUh = dot64_bcast(&a_loc[1][p][0], wh2);
            float pUz = dot64_bcast(&hd_ring[1][slot_r][0], wz2);
            stage[1][p][pr * 128 + idx]      = pUh;
            stage[1][p][pr * 128 + 64 + idx] = pUz;
        }
        __syncthreads();
        if (tid < 4) {
            fence_async();
            bulk_s2s(peer_inbox + off1 + (uint32_t)(rank << 9),
                     stage_sa   + off1 + (uint32_t)(ks << 9),
                     512u, peer_mb + mb1);
        }
        if (tid == 0) mbar_expect_tx(mb_sa + mb1, 2048u);

        // ---- prefetch both sequences (shadow)
        float xz_p20 = 0.f, xh_p20 = 0.f, xz_p21 = 0.f, xh_p21 = 0.f;
        if (tid < 64 && t + 2 < Lsz) {
            xz_p20 = __ldg(xzp + (size_t)(t + 2) * Hsz);
            xh_p20 = __ldg(xhp + (size_t)(t + 2) * Hsz);
            xz_p21 = __ldg(xzp + (size_t)(t + 2) * Hsz + LH);
            xh_p21 = __ldg(xhp + (size_t)(t + 2) * Hsz + LH);
        }

        // ================= consume seq 0, then seq 1 =====================
        if (tid < 64) {
            if (lane == 0) mbar_wait(mb_sa + mb0, q);
            __syncwarp();
            {
                const float* ib = &inbox[0][p][0];
                float sh = (ib[tid]       + ib[128 + tid])
                         + (ib[256 + tid] + ib[384 + tid]);
                float sz = (ib[64 + tid]  + ib[192 + tid])
                         + (ib[320 + tid] + ib[448 + tid]);
                float ht = tanh_fast(sh + xh_cur0);
                h0 = h0 + z0 * (ht - h0);
                float zn = sigmoid_fast(sz + xz_nxt0);
                a_loc[0][p ^ 1][tid]    = zn * h0;
                hd_ring[0][slot_w][tid] = h0;
                hsp[(size_t)t * Hsz]    = h0;
                z0 = zn;
                xh_cur0 = xh_nxt0; xz_nxt0 = xz_p20; xh_nxt0 = xh_p20;
            }
            if (lane == 0) mbar_wait(mb_sa + mb1, q);
            __syncwarp();
            {
                const float* ib = &inbox[1][p][0];
                float sh = (ib[tid]       + ib[128 + tid])
                         + (ib[256 + tid] + ib[384 + tid]);
                float sz = (ib[64 + tid]  + ib[192 + tid])
                         + (ib[320 + tid] + ib[448 + tid]);
                float ht = tanh_fast(sh + xh_cur1);
                h1 = h1 + z1 * (ht - h1);
                float zn = sigmoid_fast(sz + xz_nxt1);
                a_loc[1][p ^ 1][tid]    = zn * h1;
                hd_ring[1][slot_w][tid] = h1;
                hsp[(size_t)t * Hsz + LH] = h1;
                z1 = zn;
                xh_cur1 = xh_nxt1; xz_nxt1 = xz_p21; xh_nxt1 = xh_p21;
            }
        }
        __syncthreads();

        slot_r = (slot_r == NDELAY - 1) ? 0 : slot_r + 1;
        slot_w = (slot_w == NDELAY - 1) ? 0 : slot_w + 1;
    }

    // no CTA may exit while peer traffic targeting it may be in flight
    asm volatile("barrier.cluster.arrive.aligned;" ::: "memory");
    asm volatile("barrier.cluster.wait.aligned;" ::: "memory");
}

// Dummy so ncu (6th global launch; 2 harness launches precede ours) captures
// the scan.
__global__ void dummy_k() {}

// ---------------------------------------------------------------------------
// Launch: proj GEMMs -> dummy -> scan (16 clusters x 4 CTAs) -> head GEMM
// ---------------------------------------------------------------------------
extern "C" void kernel_launch(void* const* d_in, const int* in_sizes, int n_in,
                              void* d_out, int out_size)
{
    const float* x  = (const float*)d_in[0];
    const float* Wz = (const float*)d_in[1];
    const float* Uz = (const float*)d_in[2];
    const float* bz = (const float*)d_in[3];
    const float* Wh = (const float*)d_in[4];
    const float* Uh = (const float*)d_in[5];
    const float* bh = (const float*)d_in[6];
    const float* Wo = (const float*)d_in[7];
    const float* bo = (const float*)d_in[8];
    float* y = (float*)d_out;

    float *xz_p = nullptr, *xh_p = nullptr, *hs_p = nullptr;
    cudaGetSymbolAddress((void**)&xz_p, g_xz);
    cudaGetSymbolAddress((void**)&xh_p, g_xh);
    cudaGetSymbolAddress((void**)&hs_p, g_hs);

    const int M = Bsz * Lsz;           // 131072
    dim3 blk(256);

    gemm_bias<<<dim3(M / 64, Hsz / 64), blk>>>(x, Wz, bz, xz_p, M, Isz, Hsz);
    gemm_bias<<<dim3(M / 64, Hsz / 64), blk>>>(x, Wh, bh, xh_p, M, Isz, Hsz);

    dummy_k<<<1, 1>>>();

    mgru_scan<<<(Bsz / 2) * 4, 256>>>(xz_p, xh_p, Uz, Uh, hs_p);

    gemm_bias<<<dim3(M / 64, Osz / 64), blk>>>(hs_p, Wo, bo, y, M, Hsz, Osz);
}

// round 15
// speedup vs baseline: 1.4979x; 1.4979x over previous
#include <cuda_runtime.h>
#include <cstdint>

// Problem constants
#define Bsz 32
#define Lsz 4096
#define Isz 128
#define Hsz 256
#define Osz 128
#define NDELAY 5      // delay line length (DELAY+1)

// Scratch (static device globals: allocation-free per harness rules)
__device__ float g_xz[Bsz * Lsz * Hsz];
__device__ float g_xh[Bsz * Lsz * Hsz];
__device__ float g_hs[Bsz * Lsz * Hsz];

// ---------------------------------------------------------------------------
// Fused dual GEMM with bias: C1 = A@B1 + b1, C2 = A@B2 + b2 (shared A tile).
// A[M,K], B1/B2[K,N]; 64x64 tile, 256 threads, 4x4 micro, f32x2 accumulation.
// ---------------------------------------------------------------------------
__global__ void __launch_bounds__(256) gemm_dual_bias(
    const float* __restrict__ A,
    const float* __restrict__ B1, const float* __restrict__ b1,
    const float* __restrict__ B2, const float* __restrict__ b2,
    float* __restrict__ C1, float* __restrict__ C2,
    int M, int K, int N)
{
    __shared__ float sA[64][68];
    __shared__ float sB1[64][68];
    __shared__ float sB2[64][68];

    const int m0  = blockIdx.x << 6;
    const int n0  = blockIdx.y << 6;
    const int tid = threadIdx.x;
    const int tx  = tid & 15;
    const int ty  = tid >> 4;

    uint64_t acc1a[4], acc1b[4], acc2a[4], acc2b[4];
#pragma unroll
    for (int i = 0; i < 4; i++) { acc1a[i]=0; acc1b[i]=0; acc2a[i]=0; acc2b[i]=0; }

    for (int kk = 0; kk < K; kk += 64) {
#pragma unroll
        for (int i = 0; i < 4; i++) {
            int lin = tid + (i << 8);
            int r   = lin >> 4;
            int c   = (lin & 15) << 2;
            *(float4*)&sA[r][c]  = *(const float4*)&A [(size_t)(m0 + r) * K + kk + c];
            *(float4*)&sB1[r][c] = *(const float4*)&B1[(size_t)(kk + r) * N + n0 + c];
            *(float4*)&sB2[r][c] = *(const float4*)&B2[(size_t)(kk + r) * N + n0 + c];
        }
        __syncthreads();

#pragma unroll 8
        for (int k = 0; k < 64; k++) {
            ulonglong2 bb1 = *(const ulonglong2*)&sB1[k][tx << 2];
            ulonglong2 bb2 = *(const ulonglong2*)&sB2[k][tx << 2];
#pragma unroll
            for (int i = 0; i < 4; i++) {
                float a = sA[(ty << 2) + i][k];
                uint64_t aa;
                asm("mov.b64 %0, {%1, %1};" : "=l"(aa) : "f"(a));
                asm("fma.rn.f32x2 %0, %1, %2, %0;" : "+l"(acc1a[i]) : "l"(aa), "l"(bb1.x));
                asm("fma.rn.f32x2 %0, %1, %2, %0;" : "+l"(acc1b[i]) : "l"(aa), "l"(bb1.y));
                asm("fma.rn.f32x2 %0, %1, %2, %0;" : "+l"(acc2a[i]) : "l"(aa), "l"(bb2.x));
                asm("fma.rn.f32x2 %0, %1, %2, %0;" : "+l"(acc2b[i]) : "l"(aa), "l"(bb2.y));
            }
        }
        __syncthreads();
    }

    float4 bv1 = *(const float4*)&b1[n0 + (tx << 2)];
    float4 bv2 = *(const float4*)&b2[n0 + (tx << 2)];
#pragma unroll
    for (int i = 0; i < 4; i++) {
        float x0,x1,x2,x3;
        asm("mov.b64 {%0, %1}, %2;" : "=f"(x0), "=f"(x1) : "l"(acc1a[i]));
        asm("mov.b64 {%0, %1}, %2;" : "=f"(x2), "=f"(x3) : "l"(acc1b[i]));
        float4 o1; o1.x = x0+bv1.x; o1.y = x1+bv1.y; o1.z = x2+bv1.z; o1.w = x3+bv1.w;
        *(float4*)&C1[(size_t)(m0 + (ty << 2) + i) * N + n0 + (tx << 2)] = o1;
        asm("mov.b64 {%0, %1}, %2;" : "=f"(x0), "=f"(x1) : "l"(acc2a[i]));
        asm("mov.b64 {%0, %1}, %2;" : "=f"(x2), "=f"(x3) : "l"(acc2b[i]));
        float4 o2; o2.x = x0+bv2.x; o2.y = x1+bv2.y; o2.z = x2+bv2.z; o2.w = x3+bv2.w;
        *(float4*)&C2[(size_t)(m0 + (ty << 2) + i) * N + n0 + (tx << 2)] = o2;
    }
}

// ---------------------------------------------------------------------------
// fp32 tiled GEMM with bias (head): C = A@B + bias, f32x2 accumulation.
// ---------------------------------------------------------------------------
__global__ void __launch_bounds__(256) gemm_bias(
    const float* __restrict__ A, const float* __restrict__ Bm,
    const float* __restrict__ bias, float* __restrict__ C,
    int M, int K, int N)
{
    __shared__ float sA[64][68];
    __shared__ float sB[64][68];

    const int m0  = blockIdx.x << 6;
    const int n0  = blockIdx.y << 6;
    const int tid = threadIdx.x;
    const int tx  = tid & 15;
    const int ty  = tid >> 4;

    uint64_t acc01[4], acc23[4];
#pragma unroll
    for (int i = 0; i < 4; i++) { acc01[i] = 0; acc23[i] = 0; }

    for (int kk = 0; kk < K; kk += 64) {
#pragma unroll
        for (int i = 0; i < 4; i++) {
            int lin = tid + (i << 8);
            int r   = lin >> 4;
            int c   = (lin & 15) << 2;
            *(float4*)&sA[r][c] = *(const float4*)&A[(size_t)(m0 + r) * K + kk + c];
            *(float4*)&sB[r][c] = *(const float4*)&Bm[(size_t)(kk + r) * N + n0 + c];
        }
        __syncthreads();

#pragma unroll 16
        for (int k = 0; k < 64; k++) {
            ulonglong2 bb = *(const ulonglong2*)&sB[k][tx << 2];
#pragma unroll
            for (int i = 0; i < 4; i++) {
                float a = sA[(ty << 2) + i][k];
                uint64_t aa;
                asm("mov.b64 %0, {%1, %1};" : "=l"(aa) : "f"(a));
                asm("fma.rn.f32x2 %0, %1, %2, %0;" : "+l"(acc01[i]) : "l"(aa), "l"(bb.x));
                asm("fma.rn.f32x2 %0, %1, %2, %0;" : "+l"(acc23[i]) : "l"(aa), "l"(bb.y));
            }
        }
        __syncthreads();
    }

    float4 bb = *(const float4*)&bias[n0 + (tx << 2)];
#pragma unroll
    for (int i = 0; i < 4; i++) {
        float c0, c1, c2, c3;
        asm("mov.b64 {%0, %1}, %2;" : "=f"(c0), "=f"(c1) : "l"(acc01[i]));
        asm("mov.b64 {%0, %1}, %2;" : "=f"(c2), "=f"(c3) : "l"(acc23[i]));
        float4 o;
        o.x = c0 + bb.x; o.y = c1 + bb.y; o.z = c2 + bb.z; o.w = c3 + bb.w;
        *(float4*)&C[(size_t)(m0 + (ty << 2) + i) * N + n0 + (tx << 2)] = o;
    }
}

// ---------------------------------------------------------------------------
// Fast-math helpers (ex2/rcp approx: rel err ~1e-7)
// ---------------------------------------------------------------------------
__device__ __forceinline__ float ex2_fast(float x) {
    float r; asm("ex2.approx.f32 %0, %1;" : "=f"(r) : "f"(x)); return r;
}
__device__ __forceinline__ float rcp_fast(float x) {
    float r; asm("rcp.approx.f32 %0, %1;" : "=f"(r) : "f"(x)); return r;
}
__device__ __forceinline__ float sigmoid_fast(float x) {
    return rcp_fast(1.f + ex2_fast(-1.4426950408889634f * x));
}
__device__ __forceinline__ float tanh_fast(float x) {
    float e = ex2_fast(2.885390081777927f * x);
    return (e - 1.f) * rcp_fast(e + 1.f);
}

// Packed f32x2 dot over 64 floats; all lanes read the SAME addresses
// (whole-warp broadcast -> conflict-free, 1 wavefront per LDS.128).
__device__ __forceinline__ float dot64_bcast(const float* p, const uint64_t* w) {
    const ulonglong2* v = (const ulonglong2*)p;
    uint64_t a0 = 0, a1 = 0, a2 = 0, a3 = 0;
#pragma unroll
    for (int j = 0; j < 8; j++) {
        ulonglong2 t = v[j];
        asm("fma.rn.f32x2 %0, %1, %2, %0;" : "+l"(a0) : "l"(t.x), "l"(w[2*j]));
        asm("fma.rn.f32x2 %0, %1, %2, %0;" : "+l"(a1) : "l"(t.y), "l"(w[2*j+1]));
    }
#pragma unroll
    for (int j = 8; j < 16; j++) {
        ulonglong2 t = v[j];
        asm("fma.rn.f32x2 %0, %1, %2, %0;" : "+l"(a2) : "l"(t.x), "l"(w[2*j]));
        asm("fma.rn.f32x2 %0, %1, %2, %0;" : "+l"(a3) : "l"(t.y), "l"(w[2*j+1]));
    }
    uint64_t s01, s23, s;
    asm("add.rn.f32x2 %0, %1, %2;" : "=l"(s01) : "l"(a0), "l"(a1));
    asm("add.rn.f32x2 %0, %1, %2;" : "=l"(s23) : "l"(a2), "l"(a3));
    asm("add.rn.f32x2 %0, %1, %2;" : "=l"(s)   : "l"(s01), "l"(s23));
    float lo, hi;
    asm("mov.b64 {%0, %1}, %2;" : "=f"(lo), "=f"(hi) : "l"(s));
    return lo + hi;
}

__device__ __forceinline__ uint64_t pack2(float lo, float hi) {
    uint64_t r; asm("mov.b64 %0, {%1, %2};" : "=l"(r) : "f"(lo), "f"(hi)); return r;
}

__device__ __forceinline__ void mbar_expect_tx(uint32_t mbar, uint32_t bytes) {
    asm volatile("mbarrier.arrive.expect_tx.shared.b64 _, [%0], %1;"
                 :: "r"(mbar), "r"(bytes) : "memory");
}

__device__ __forceinline__ void mbar_wait(uint32_t mbar, uint32_t parity) {
    asm volatile(
        "{\n\t"
        ".reg .pred P;\n\t"
        "WAIT_%=:\n\t"
        "mbarrier.try_wait.parity.acquire.cluster.shared::cta.b64 P, [%0], %1, 10000000;\n\t"
        "@!P bra WAIT_%=;\n\t"
        "}"
        :: "r"(mbar), "r"(parity) : "memory");
}

// DSMEM bulk copy: local smem -> peer smem, complete_tx to peer's mbarrier.
__device__ __forceinline__ void bulk_s2s(uint32_t dst, uint32_t src,
                                         uint32_t bytes, uint32_t mbar) {
    asm volatile(
        "cp.async.bulk.shared::cluster.shared::cta.mbarrier::complete_tx::bytes "
        "[%0], [%1], %2, [%3];"
        :: "r"(dst), "r"(src), "r"(bytes), "r"(mbar) : "memory");
}

__device__ __forceinline__ void fence_async() {
    asm volatile("fence.proxy.async.shared::cta;" ::: "memory");
}

// ---------------------------------------------------------------------------
// Sequential MGRU scan — R10 dataflow + Uz partial in the flight shadow.
//
// 32 clusters x 4 CTAs, one cluster per batch row. CTA r owns state indices
// G = [64r, 64r+64) both as hidden columns and as k-rows of Uz/Uh. Thread
// tid (jp = tid) computes the k-partials over G:
//   pUh(t)   = sum_{k in G} a_k(t)   Uh[k,jp]  (pre-push, critical path)
//   pUz(t+1) = sum_{k in G} h_k(t-3) Uz[k,jp]  (computed in step t's SHADOW,
//              after the push, carried in a register; packet t+1 feeds
//              z(t+2) which uses h(t+2-5) = h(t-3))
// Packet t per destination CTA: [pUh 64 | pUz 64] floats = 512B, staged,
// ONE full __syncthreads, tid<4 bulk-push onto mb[t&1] (2048 tx-bytes).
// Exchange structure is verbatim R10 (proven fastest across R11-R14).
//
// Buffer-reuse safety (verbatim R10 chains, plus the shadow slot):
//   a_loc[p]   read by dots at t; rewritten at update(t+1) after wait(t+1).
//   stage[p]   engine-read at push(t); rewritten at t+2 after wait(t+1)
//              <- peer push(t+1) <- peer end-sync(t) <- peer wait(t).
//   inbox[p]   owner-read at t; peer overwrite at t+2 follows peer
//              wait(t+1) <- our push(t+1) <- our end-sync(t).
//   hd_ring    slot s%5 written at update(s); shadow at step t reads slot
//              (t+2)%5 = h(t-3) (3 syncs of slack; update(t) writes slot
//              t%5, disjoint from (t+2)%5).
// ---------------------------------------------------------------------------
__global__ void __launch_bounds__(256, 1) __cluster_dims__(4, 1, 1)
mgru_scan(const float* __restrict__ xz, const float* __restrict__ xh,
          const float* __restrict__ Uz, const float* __restrict__ Uh,
          float* __restrict__ hs)
{
    __shared__ __align__(16) float a_loc[2][64];        // a(t) local chunk
    __shared__ __align__(16) float hd_ring[NDELAY][64]; // local h history
    __shared__ __align__(16) float stage[2][512];       // [p][dst*128: pUh|pUz]
    __shared__ __align__(16) float inbox[2][512];       // [p][src*128: pUh|pUz]
    __shared__ __align__(8) unsigned long long mb[2];

    const int rank = blockIdx.x & 3;
    const int b    = blockIdx.x >> 2;
    const int tid  = threadIdx.x;
    const int lane = tid & 31;
    const int jp   = tid;                 // partial column (global, 0..255)
    const int pr   = tid >> 6;            // destination CTA (owner of jp)
    const int idx  = tid & 63;            // index within destination slice
    const int ks   = tid & 3;             // push peer for tid<4

    // Register-resident weight slices: rows k in G, column jp.
    uint64_t wz2[32], wh2[32];
    {
        const float* uz = Uz + (size_t)(rank * 64) * Hsz + jp;
        const float* uh = Uh + (size_t)(rank * 64) * Hsz + jp;
#pragma unroll
        for (int i = 0; i < 32; i++) {
            wz2[i] = pack2(uz[(size_t)(2*i) * Hsz], uz[(size_t)(2*i+1) * Hsz]);
            wh2[i] = pack2(uh[(size_t)(2*i) * Hsz], uh[(size_t)(2*i+1) * Hsz]);
        }
    }

    if (tid == 0) {
        uint32_t m0 = (uint32_t)__cvta_generic_to_shared(&mb[0]);
        asm volatile("mbarrier.init.shared.b64 [%0], 1;" :: "r"(m0) : "memory");
        asm volatile("mbarrier.init.shared.b64 [%0], 1;" :: "r"(m0 + 8) : "memory");
    }
    for (int i = tid; i < 2 * 64;      i += 256) (&a_loc[0][0])[i]   = 0.f;
    for (int i = tid; i < NDELAY * 64; i += 256) (&hd_ring[0][0])[i] = 0.f;
    for (int i = tid; i < 2 * 512;     i += 256) (&stage[0][0])[i]   = 0.f;
    for (int i = tid; i < 2 * 512;     i += 256) (&inbox[0][0])[i]   = 0.f;
    __syncthreads();
    // all CTAs' mbarriers + zeroed buffers visible before any DSMEM traffic
    asm volatile("barrier.cluster.arrive.aligned;" ::: "memory");
    asm volatile("barrier.cluster.wait.aligned;" ::: "memory");

    const uint32_t stage_sa = (uint32_t)__cvta_generic_to_shared(&stage[0][0]);
    const uint32_t inbox_sa = (uint32_t)__cvta_generic_to_shared(&inbox[0][0]);
    const uint32_t mb_sa    = (uint32_t)__cvta_generic_to_shared(&mb[0]);
    uint32_t peer_inbox = 0, peer_mb = 0;   // in CTA `ks`'s SMEM (tid 0..3)
    asm("mapa.shared::cluster.u32 %0, %1, %2;" : "=r"(peer_inbox) : "r"(inbox_sa), "r"(ks));
    asm("mapa.shared::cluster.u32 %0, %1, %2;" : "=r"(peer_mb)    : "r"(mb_sa),    "r"(ks));

    // Column-owner state (threads 0..63): jglob = 64*rank + tid
    const int jglob = rank * 64 + tid;    // valid for tid < 64
    const float* xzp = xz + (size_t)b * Lsz * Hsz + jglob;
    const float* xhp = xh + (size_t)b * Lsz * Hsz + jglob;
    float*       hsp = hs + (size_t)b * Lsz * Hsz + jglob;

    float h = 0.f, z = 0.f;
    float xh_cur = 0.f, xz_nxt = 0.f, xh_nxt = 0.f;
    if (tid < 64) {
        xh_cur = xhp[0];
        xz_nxt = xzp[Hsz];
        xh_nxt = xhp[Hsz];
        z      = sigmoid_fast(xzp[0]);   // z(0): h(-5) = 0
        // a(0) = z(0)*h(-1) = 0 -> a_loc[0] already zeroed
    }

    float pUz_next = 0.f;   // packet 0 pUz: z(1) uses h(-4) = 0

    int slot_s = 2;  // (t+2)%5 : shadow-read h(t-3) for packet t+1
    int slot_w = 0;  // t%5     : write h(t)

    for (int t = 0; t < Lsz; ++t) {
        const int p = t & 1;
        const uint32_t boff = (uint32_t)(p << 3);
        const uint32_t pb   = (uint32_t)(p << 11);   // p*512 floats in bytes

        // ---- Uh partial from the local a(t) chunk (critical path);
        //      pUz for this packet was computed in last step's shadow.
        {
            float pUh = dot64_bcast(&a_loc[p][0], wh2);
            stage[p][pr * 128 + idx]      = pUh;
            stage[p][pr * 128 + 64 + idx] = pUz_next;
        }
        __syncthreads();

        // ---- push partial slices to all 4 CTAs (512B each)
        if (tid < 4) {
            fence_async();
            bulk_s2s(peer_inbox + pb + (uint32_t)(rank << 9),
                     stage_sa + pb + (uint32_t)(ks << 9),
                     512u, peer_mb + boff);
        }
        if (tid == 0) mbar_expect_tx(mb_sa + boff, 2048u);

        // ---- shadow: pUz for packet t+1 (reads h(t-3)); gmem prefetch
        float pUz_sh = dot64_bcast(&hd_ring[slot_s][0], wz2);
        float xz_p2 = 0.f, xh_p2 = 0.f;
        if (tid < 64 && t + 2 < Lsz) {
            xz_p2 = __ldg(xzp + (size_t)(t + 2) * Hsz);
            xh_p2 = __ldg(xhp + (size_t)(t + 2) * Hsz);
        }

        // ---- owners: acquire-wait, reduce 4 partials, update state
        if (tid < 64) {
            if (lane == 0) mbar_wait(mb_sa + boff, (uint32_t)((t >> 1) & 1));
            __syncwarp();

            const float* ib = &inbox[p][0];
            float sh = (ib[tid]       + ib[128 + tid])
                     + (ib[256 + tid] + ib[384 + tid]);
            float sz = (ib[64 + tid]  + ib[192 + tid])
                     + (ib[320 + tid] + ib[448 + tid]);
            float ht = tanh_fast(sh + xh_cur);
            h = h + z * (ht - h);                  // h(t)
            float zn = sigmoid_fast(sz + xz_nxt);  // z(t+1)

            a_loc[p ^ 1][tid]    = zn * h;         // a(t+1) local chunk
            hd_ring[slot_w][tid] = h;              // h(t) into ring
            hsp[(size_t)t * Hsz] = h;

            z = zn;
            xh_cur = xh_nxt;
            xz_nxt = xz_p2;
            xh_nxt = xh_p2;
        }
        __syncthreads();

        pUz_next = pUz_sh;
        slot_s = (slot_s == NDELAY - 1) ? 0 : slot_s + 1;
        slot_w = (slot_w == NDELAY - 1) ? 0 : slot_w + 1;
    }

    // no CTA may exit while peer traffic targeting it may be in flight
    asm volatile("barrier.cluster.arrive.aligned;" ::: "memory");
    asm volatile("barrier.cluster.wait.aligned;" ::: "memory");
}

// Dummies so ncu (6th global launch; 2 harness launches precede ours)
// captures the scan: launches are [dual-gemm, dummy, dummy, scan, head].
__global__ void dummy_k() {}

// ---------------------------------------------------------------------------
// Launch: fused proj GEMM -> dummies -> scan -> head GEMM
// ---------------------------------------------------------------------------
extern "C" void kernel_launch(void* const* d_in, const int* in_sizes, int n_in,
                              void* d_out, int out_size)
{
    const float* x  = (const float*)d_in[0];
    const float* Wz = (const float*)d_in[1];
    const float* Uz = (const float*)d_in[2];
    const float* bz = (const float*)d_in[3];
    const float* Wh = (const float*)d_in[4];
    const float* Uh = (const float*)d_in[5];
    const float* bh = (const float*)d_in[6];
    const float* Wo = (const float*)d_in[7];
    const float* bo = (const float*)d_in[8];
    float* y = (float*)d_out;

    float *xz_p = nullptr, *xh_p = nullptr, *hs_p = nullptr;
    cudaGetSymbolAddress((void**)&xz_p, g_xz);
    cudaGetSymbolAddress((void**)&xh_p, g_xh);
    cudaGetSymbolAddress((void**)&hs_p, g_hs);

    const int M = Bsz * Lsz;           // 131072
    dim3 blk(256);

    // xz = x@Wz + bz AND xh = x@Wh + bh in one pass over x
    gemm_dual_bias<<<dim3(M / 64, Hsz / 64), blk>>>(
        x, Wz, bz, Wh, bh, xz_p, xh_p, M, Isz, Hsz);

    dummy_k<<<1, 1>>>();
    dummy_k<<<1, 1>>>();

    mgru_scan<<<Bsz * 4, 256>>>(xz_p, xh_p, Uz, Uh, hs_p);

    gemm_bias<<<dim3(M / 64, Osz / 64), blk>>>(hs_p, Wo, bo, y, M, Hsz, Osz);
}